// round 12
// baseline (speedup 1.0000x reference)
#include <cuda_runtime.h>
#include <cuda_fp16.h>
#include <math.h>
#include <stdint.h>

#define B_ 128
#define L_ 512
#define N_ 1023
#define T_ 511
#define D_ 256
#define C_ 511
#define EPS_ 1e-6f

// fp32 master copy (compose iterates on this) + fp16 mirror for the GEMM.
__device__ float  g_vec[(size_t)B_ * N_ * D_];     // 134 MB
__device__ __half g_vec16[(size_t)B_ * N_ * D_];   // 67 MB
__device__ __half g_W16[512 * 256];                // W fp16, zero-padded row 511

__device__ __forceinline__ uint32_t smem_to_u32(const void* p) {
    uint32_t a;
    asm("{ .reg .u64 t; cvta.to.shared.u64 t, %1; cvt.u32.u64 %0, t; }"
        : "=r"(a) : "l"(p));
    return a;
}

// ---------------------------------------------------------------------------
// Zero both node-vector buffers
// ---------------------------------------------------------------------------
__global__ void zero_kernel() {
    size_t t32 = (size_t)B_ * N_ * D_ / 4;
    float4* p = reinterpret_cast<float4*>(g_vec);
    float4 z = make_float4(0.f, 0.f, 0.f, 0.f);
    for (size_t i = (size_t)blockIdx.x * blockDim.x + threadIdx.x; i < t32;
         i += (size_t)gridDim.x * blockDim.x)
        p[i] = z;
    size_t t16 = (size_t)B_ * N_ * D_ / 8;
    uint4* q = reinterpret_cast<uint4*>(g_vec16);
    uint4 zz = make_uint4(0u, 0u, 0u, 0u);
    for (size_t i = (size_t)blockIdx.x * blockDim.x + threadIdx.x; i < t16;
         i += (size_t)gridDim.x * blockDim.x)
        q[i] = zz;
}

// ---------------------------------------------------------------------------
// Pack W (C,D) fp32 -> fp16, zero-padding to 512 rows.
// ---------------------------------------------------------------------------
__global__ void pack_w_kernel(const float* __restrict__ W) {
    int idx = blockIdx.x * 256 + threadIdx.x;
    int row = idx >> 8;
    int k   = idx & 255;
    g_W16[idx] = __float2half((row < C_) ? W[row * 256 + k] : 0.f);
}

// ---------------------------------------------------------------------------
// Scatter normalized embedding rows into g_vec + g_vec16. One warp per leaf.
// ---------------------------------------------------------------------------
__global__ void embed_kernel(const int* __restrict__ leaf_id,
                             const int* __restrict__ mask,
                             const float* __restrict__ emb) {
    int leaf = blockIdx.x * 8 + (threadIdx.x >> 5);
    int lane = threadIdx.x & 31;
    if (leaf >= B_ * L_) return;
    if (mask[leaf] == 0) return;
    int b = leaf / L_;
    int node = leaf_id[2 * leaf + 0];
    int vid  = leaf_id[2 * leaf + 1];
    if ((unsigned)node >= (unsigned)N_) return;
    const float4* src = reinterpret_cast<const float4*>(emb + (size_t)vid * D_);
    float4 v0 = src[lane];
    float4 v1 = src[lane + 32];
    float ss = v0.x * v0.x + v0.y * v0.y + v0.z * v0.z + v0.w * v0.w
             + v1.x * v1.x + v1.y * v1.y + v1.z * v1.z + v1.w * v1.w;
#pragma unroll
    for (int o = 16; o > 0; o >>= 1) ss += __shfl_xor_sync(0xffffffffu, ss, o);
    float inv = 1.f / (sqrtf(ss) + EPS_);
    v0.x *= inv; v0.y *= inv; v0.z *= inv; v0.w *= inv;
    v1.x *= inv; v1.y *= inv; v1.z *= inv; v1.w *= inv;
    size_t base = ((size_t)b * N_ + node) * D_;
    float4* dst = reinterpret_cast<float4*>(g_vec + base);
    dst[lane]      = v0;
    dst[lane + 32] = v1;
    __half2* dst16 = reinterpret_cast<__half2*>(g_vec16 + base);
    dst16[2 * lane + 0]  = __float22half2_rn(make_float2(v0.x, v0.y));
    dst16[2 * lane + 1]  = __float22half2_rn(make_float2(v0.z, v0.w));
    dst16[2 * lane + 64] = __float22half2_rn(make_float2(v1.x, v1.y));
    dst16[2 * lane + 65] = __float22half2_rn(make_float2(v1.z, v1.w));
}

// ---------------------------------------------------------------------------
// Tree composition with GROUPED concurrent steps.
// One block per batch. Up to 4 consecutive, pairwise NON-CONFLICTING steps run
// concurrently, one per 64-thread subgroup (2 warps). Conflict(i<j):
//   (typ_i>0 && typ_j>0) && (p_i in {l_j, r_j, p_j}  ||  p_j in {l_i, r_i})
// (type-0 steps are exact no-ops: never conflict). Grouping is computed
// redundantly and deterministically by every thread from smem.
// Subgroup step: stage a,b -> bar.sync(s+1,64) -> full 256-j rolling-window
// correlation per thread (k = 4u..4u+3) -> shfl+bar norm -> float4 writes.
// One block-wide __syncthreads per GROUP (orders gmem writes for next group).
// ---------------------------------------------------------------------------
__global__ void __launch_bounds__(256) compose_kernel(const int* __restrict__ comp) {
    __shared__ int sinfo[T_ * 4];
    __shared__ __align__(16) float sa[4][256];
    __shared__ float sbw[4][648];
    __shared__ float sred[4][2];

    int b = blockIdx.x;
    int tid = threadIdx.x;
    float*  v   = g_vec   + (size_t)b * N_ * D_;
    __half* v16 = g_vec16 + (size_t)b * N_ * D_;

    for (int i = tid; i < T_ * 4; i += 256)
        sinfo[i] = comp[(size_t)b * T_ * 4 + i];
    __syncthreads();

    const int s = tid >> 6;          // subgroup 0..3
    const int u = tid & 63;          // thread-in-subgroup
    const int P0 = 5 * u;            // swizzled window base for k = 4u

    int ts = 0;
    while (ts < T_) {
        // ---- deterministic greedy grouping (identical in all threads)
        int gsz = 1;
#pragma unroll 1
        while (gsz < 4 && ts + gsz < T_) {
            const int* ci = &sinfo[4 * (ts + gsz)];
            int typc = ci[0], pc = ci[1], lc = ci[2], rc = ci[3];
            bool conf = false;
#pragma unroll 1
            for (int i = 0; i < gsz; ++i) {
                const int* si = &sinfo[4 * (ts + i)];
                int typi = si[0], pi = si[1], li = si[2], ri = si[3];
                if (typi > 0 && typc > 0 &&
                    (pi == lc || pi == rc || pi == pc || pc == li || pc == ri))
                    conf = true;
            }
            if (conf) break;
            ++gsz;
        }

        if (s < gsz) {
            const int* si = &sinfo[4 * (ts + s)];
            int typ = si[0], p = si[1], l = si[2], r = si[3];
            if (typ == 1) {
                float4 lv = *reinterpret_cast<const float4*>(v + (size_t)l * D_ + 4 * u);
                *reinterpret_cast<float4*>(v + (size_t)p * D_ + 4 * u) = lv;
                __half2* d16 = reinterpret_cast<__half2*>(v16 + (size_t)p * D_ + 4 * u);
                d16[0] = __float22half2_rn(make_float2(lv.x, lv.y));
                d16[1] = __float22half2_rn(make_float2(lv.z, lv.w));
            } else if (typ == 2) {
                float4 lv = *reinterpret_cast<const float4*>(v + (size_t)l * D_ + 4 * u);
                float4 rv = *reinterpret_cast<const float4*>(v + (size_t)r * D_ + 4 * u);
                *reinterpret_cast<float4*>(&sa[s][4 * u]) = lv;
                float* bw = sbw[s];
                int base = 5 * u;               // phys(4u) = 4u + u
                bw[base + 0] = rv.x; bw[base + 1] = rv.y;
                bw[base + 2] = rv.z; bw[base + 3] = rv.w;
                bw[base + 320] = rv.x; bw[base + 321] = rv.y;   // dup at i+256
                bw[base + 322] = rv.z; bw[base + 323] = rv.w;
                asm volatile("bar.sync %0, 64;" :: "r"(s + 1) : "memory");

                // rolling-window correlation, k = 4u..4u+3, j = 0..255
                float w0 = bw[P0 + 0];
                float w1 = bw[P0 + 1];
                float w2 = bw[P0 + 2];
                float w3 = bw[P0 + 3];
                float a0 = 0.f, a1 = 0.f, a2 = 0.f, a3 = 0.f;
                const float* ap = sa[s];
#pragma unroll 8
                for (int uu = 0; uu < 64; ++uu) {
                    float4 aq = *reinterpret_cast<const float4*>(ap + 4 * uu);
                    int Pu = P0 + 5 * (uu + 1);
                    a0 += aq.x * w0; a1 += aq.x * w1; a2 += aq.x * w2; a3 += aq.x * w3;
                    float n0 = bw[Pu + 0];
                    a0 += aq.y * w1; a1 += aq.y * w2; a2 += aq.y * w3; a3 += aq.y * n0;
                    float n1 = bw[Pu + 1];
                    a0 += aq.z * w2; a1 += aq.z * w3; a2 += aq.z * n0; a3 += aq.z * n1;
                    float n2 = bw[Pu + 2];
                    a0 += aq.w * w3; a1 += aq.w * n0; a2 += aq.w * n1; a3 += aq.w * n2;
                    float n3 = bw[Pu + 3];
                    w0 = n0; w1 = n1; w2 = n2; w3 = n3;
                }

                float ss = a0 * a0 + a1 * a1 + a2 * a2 + a3 * a3;
#pragma unroll
                for (int o = 16; o > 0; o >>= 1)
                    ss += __shfl_xor_sync(0xffffffffu, ss, o);
                if ((u & 31) == 0) sred[s][u >> 5] = ss;
                asm volatile("bar.sync %0, 64;" :: "r"(s + 1) : "memory");
                float tss = sred[s][0] + sred[s][1];
                float den = sqrtf(tss) + EPS_;
                float4 o4 = make_float4(a0 / den, a1 / den, a2 / den, a3 / den);
                *reinterpret_cast<float4*>(v + (size_t)p * D_ + 4 * u) = o4;
                __half2* d16 = reinterpret_cast<__half2*>(v16 + (size_t)p * D_ + 4 * u);
                d16[0] = __float22half2_rn(make_float2(o4.x, o4.y));
                d16[1] = __float22half2_rn(make_float2(o4.z, o4.w));
            }
            // typ == 0: exact no-op
        }

        ts += gsz;
        __syncthreads();   // group boundary: writes visible, smem reusable
    }
}

// ---------------------------------------------------------------------------
// fp16 mma.sync m16n8k16 GEMM (R11 — best measured).
// BM=128, BN=128, BK=32, 256 threads (8 warps: 4 along M x 2 along N).
// ---------------------------------------------------------------------------
#define GS_H 40                      // smem row stride in halfs (32 + 8 pad)
#define STAGE_H (256 * GS_H)         // halfs per stage

__device__ __forceinline__ void cp16(uint32_t dst, const void* src) {
    asm volatile("cp.async.ca.shared.global [%0], [%1], 16;"
                 :: "r"(dst), "l"(src) : "memory");
}
__device__ __forceinline__ void cp_commit() {
    asm volatile("cp.async.commit_group;" ::: "memory");
}
__device__ __forceinline__ void cp_wait0() {
    asm volatile("cp.async.wait_group 0;" ::: "memory");
}
__device__ __forceinline__ void mma_f16(float* d, const uint32_t* a,
                                        uint32_t b0, uint32_t b1) {
    asm volatile(
        "mma.sync.aligned.m16n8k16.row.col.f32.f16.f16.f32 "
        "{%0,%1,%2,%3}, {%4,%5,%6,%7}, {%8,%9}, {%0,%1,%2,%3};"
        : "+f"(d[0]), "+f"(d[1]), "+f"(d[2]), "+f"(d[3])
        : "r"(a[0]), "r"(a[1]), "r"(a[2]), "r"(a[3]), "r"(b0), "r"(b1));
}

extern __shared__ __half gm_smem[];

__global__ void __launch_bounds__(256, 2) gemm_mma_kernel(const float* __restrict__ bias,
                                                          float* __restrict__ out) {
    const __half* A = g_vec16;
    int tid = threadIdx.x;
    int wid = tid >> 5;
    int lane = tid & 31;
    int qr = lane >> 2;
    int c4 = lane & 3;
    int wm = wid & 3;
    int wn = wid >> 2;

    int n0 = blockIdx.x * 128;
    size_t m0 = (size_t)blockIdx.y * 128;

    int lrow = tid >> 1;
    int lseg = tid & 1;
    const __half* asrc = A + (m0 + lrow) * D_ + lseg * 16;
    const __half* bsrc = g_W16 + (size_t)(n0 + lrow) * D_ + lseg * 16;

    uint32_t smbase = smem_to_u32(gm_smem);
    uint32_t ldstA = smbase + (uint32_t)(lrow * GS_H + lseg * 16) * 2;
    uint32_t ldstB = ldstA + 128 * GS_H * 2;

#pragma unroll
    for (int q = 0; q < 2; ++q) {
        cp16(ldstA + q * 16, asrc + q * 8);
        cp16(ldstB + q * 16, bsrc + q * 8);
    }
    cp_commit();

    float acc[2][8][4];
#pragma unroll
    for (int mt = 0; mt < 2; ++mt)
#pragma unroll
        for (int nt = 0; nt < 8; ++nt)
#pragma unroll
            for (int w = 0; w < 4; ++w) acc[mt][nt][w] = 0.f;

    cp_wait0();
    __syncthreads();

    for (int bk = 0; bk < 8; ++bk) {
        int cur = bk & 1;
        if (bk < 7) {
            int nxt = cur ^ 1;
            uint32_t dA = ldstA + (uint32_t)(nxt * STAGE_H) * 2;
            uint32_t dB = ldstB + (uint32_t)(nxt * STAGE_H) * 2;
            const __half* as = asrc + (bk + 1) * 32;
            const __half* bs = bsrc + (bk + 1) * 32;
#pragma unroll
            for (int q = 0; q < 2; ++q) {
                cp16(dA + q * 16, as + q * 8);
                cp16(dB + q * 16, bs + q * 8);
            }
            cp_commit();
        }

        const __half* sA = gm_smem + cur * STAGE_H;
        const __half* sB = sA + 128 * GS_H;
        int ra = wm * 32 + qr;
        int nb = wn * 64 + qr;
#pragma unroll
        for (int sft = 0; sft < 2; ++sft) {
            int kb = 16 * sft + 2 * c4;
            uint32_t af[2][4];
#pragma unroll
            for (int mt = 0; mt < 2; ++mt) {
                int r0 = ra + mt * 16;
                af[mt][0] = *reinterpret_cast<const uint32_t*>(&sA[r0 * GS_H + kb]);
                af[mt][1] = *reinterpret_cast<const uint32_t*>(&sA[(r0 + 8) * GS_H + kb]);
                af[mt][2] = *reinterpret_cast<const uint32_t*>(&sA[r0 * GS_H + kb + 8]);
                af[mt][3] = *reinterpret_cast<const uint32_t*>(&sA[(r0 + 8) * GS_H + kb + 8]);
            }
#pragma unroll
            for (int nt = 0; nt < 8; ++nt) {
                int n = nb + nt * 8;
                uint32_t b0 = *reinterpret_cast<const uint32_t*>(&sB[n * GS_H + kb]);
                uint32_t b1 = *reinterpret_cast<const uint32_t*>(&sB[n * GS_H + kb + 8]);
                mma_f16(acc[0][nt], af[0], b0, b1);
                mma_f16(acc[1][nt], af[1], b0, b1);
            }
        }

        if (bk < 7) cp_wait0();
        __syncthreads();
    }

#pragma unroll
    for (int nt = 0; nt < 8; ++nt) {
        int col = n0 + wn * 64 + nt * 8 + 2 * c4;
        if (col >= C_) continue;
        bool c1ok = (col + 1) < C_;
        float b0v = bias[col];
        float b1v = c1ok ? bias[col + 1] : 0.f;
#pragma unroll
        for (int mt = 0; mt < 2; ++mt) {
            size_t m = m0 + wm * 32 + mt * 16 + qr;
            float* o0 = out + m * C_ + col;
            o0[0] = acc[mt][nt][0] + b0v;
            if (c1ok) o0[1] = acc[mt][nt][1] + b1v;
            float* o1 = out + (m + 8) * C_ + col;
            o1[0] = acc[mt][nt][2] + b0v;
            if (c1ok) o1[1] = acc[mt][nt][3] + b1v;
        }
    }
}

// ---------------------------------------------------------------------------
extern "C" void kernel_launch(void* const* d_in, const int* in_sizes, int n_in,
                              void* d_out, int out_size) {
    const int*   leaf_id = (const int*)d_in[1];    // (B,L,2) int32
    const int*   mask    = (const int*)d_in[2];    // (B,L)   int32
    const int*   comp    = (const int*)d_in[3];    // (B,T,4) int32
    const float* emb     = (const float*)d_in[4];  // (V,D)
    const float* W       = (const float*)d_in[5];  // (C,D)
    const float* bias    = (const float*)d_in[6];  // (C,)
    float* out = (float*)d_out;                    // (B,N,C)

    zero_kernel<<<2048, 256>>>();
    pack_w_kernel<<<512, 256>>>(W);
    embed_kernel<<<(B_ * L_ + 7) / 8, 256>>>(leaf_id, mask, emb);
    compose_kernel<<<B_, 256>>>(comp);

    static bool attr_set = false;
    if (!attr_set) {
        cudaFuncSetAttribute(gemm_mma_kernel,
                             cudaFuncAttributeMaxDynamicSharedMemorySize,
                             2 * STAGE_H * 2);
        attr_set = true;
    }
    dim3 grid(4, 1023);
    gemm_mma_kernel<<<grid, 256, 2 * STAGE_H * 2>>>(bias, out);
}

// round 13
// speedup vs baseline: 1.2247x; 1.2247x over previous
#include <cuda_runtime.h>
#include <cuda_fp16.h>
#include <math.h>
#include <stdint.h>

#define B_ 128
#define L_ 512
#define N_ 1023
#define T_ 511
#define D_ 256
#define C_ 511
#define EPS_ 1e-6f

// fp32 master copy (compose iterates on this) + fp16 mirror for the GEMM.
__device__ float  g_vec[(size_t)B_ * N_ * D_];     // 134 MB
__device__ __half g_vec16[(size_t)B_ * N_ * D_];   // 67 MB
__device__ __half g_W16[512 * 256];                // W fp16, zero-padded row 511

__device__ __forceinline__ uint32_t smem_to_u32(const void* p) {
    uint32_t a;
    asm("{ .reg .u64 t; cvta.to.shared.u64 t, %1; cvt.u32.u64 %0, t; }"
        : "=r"(a) : "l"(p));
    return a;
}

// ---------------------------------------------------------------------------
// Zero both node-vector buffers
// ---------------------------------------------------------------------------
__global__ void zero_kernel() {
    size_t t32 = (size_t)B_ * N_ * D_ / 4;
    float4* p = reinterpret_cast<float4*>(g_vec);
    float4 z = make_float4(0.f, 0.f, 0.f, 0.f);
    for (size_t i = (size_t)blockIdx.x * blockDim.x + threadIdx.x; i < t32;
         i += (size_t)gridDim.x * blockDim.x)
        p[i] = z;
    size_t t16 = (size_t)B_ * N_ * D_ / 8;
    uint4* q = reinterpret_cast<uint4*>(g_vec16);
    uint4 zz = make_uint4(0u, 0u, 0u, 0u);
    for (size_t i = (size_t)blockIdx.x * blockDim.x + threadIdx.x; i < t16;
         i += (size_t)gridDim.x * blockDim.x)
        q[i] = zz;
}

// ---------------------------------------------------------------------------
// Pack W (C,D) fp32 -> fp16, zero-padding to 512 rows.
// ---------------------------------------------------------------------------
__global__ void pack_w_kernel(const float* __restrict__ W) {
    int idx = blockIdx.x * 256 + threadIdx.x;
    int row = idx >> 8;
    int k   = idx & 255;
    g_W16[idx] = __float2half((row < C_) ? W[row * 256 + k] : 0.f);
}

// ---------------------------------------------------------------------------
// Scatter normalized embedding rows into g_vec + g_vec16. One warp per leaf.
// ---------------------------------------------------------------------------
__global__ void embed_kernel(const int* __restrict__ leaf_id,
                             const int* __restrict__ mask,
                             const float* __restrict__ emb) {
    int leaf = blockIdx.x * 8 + (threadIdx.x >> 5);
    int lane = threadIdx.x & 31;
    if (leaf >= B_ * L_) return;
    if (mask[leaf] == 0) return;
    int b = leaf / L_;
    int node = leaf_id[2 * leaf + 0];
    int vid  = leaf_id[2 * leaf + 1];
    if ((unsigned)node >= (unsigned)N_) return;
    const float4* src = reinterpret_cast<const float4*>(emb + (size_t)vid * D_);
    float4 v0 = src[lane];
    float4 v1 = src[lane + 32];
    float ss = v0.x * v0.x + v0.y * v0.y + v0.z * v0.z + v0.w * v0.w
             + v1.x * v1.x + v1.y * v1.y + v1.z * v1.z + v1.w * v1.w;
#pragma unroll
    for (int o = 16; o > 0; o >>= 1) ss += __shfl_xor_sync(0xffffffffu, ss, o);
    float inv = 1.f / (sqrtf(ss) + EPS_);
    v0.x *= inv; v0.y *= inv; v0.z *= inv; v0.w *= inv;
    v1.x *= inv; v1.y *= inv; v1.z *= inv; v1.w *= inv;
    size_t base = ((size_t)b * N_ + node) * D_;
    float4* dst = reinterpret_cast<float4*>(g_vec + base);
    dst[lane]      = v0;
    dst[lane + 32] = v1;
    __half2* dst16 = reinterpret_cast<__half2*>(g_vec16 + base);
    dst16[2 * lane + 0]  = __float22half2_rn(make_float2(v0.x, v0.y));
    dst16[2 * lane + 1]  = __float22half2_rn(make_float2(v0.z, v0.w));
    dst16[2 * lane + 64] = __float22half2_rn(make_float2(v1.x, v1.y));
    dst16[2 * lane + 65] = __float22half2_rn(make_float2(v1.z, v1.w));
}

// ---------------------------------------------------------------------------
// Sequential tree composition (R11 structure) with packed f32x2 inner loop.
// Thread (t = tid&63, g = tid>>6): outputs k = 4t..4t+3 over j in [64g,+64).
//   acc_i (f32x2) += (a[j], a[j+1]) * (b[m+..], b[m+..+1]),  m = 4t + j0
// Even-offset pairs come straight from 16B LDS (natural layout, conflict-free:
// lane stride 16B covers all banks); odd-offset pairs are built in registers
// from neighboring halves (mov.b64 pack/unpack) — no second smem array.
// ---------------------------------------------------------------------------
#define PK2(dst, lo, hi) \
    asm("mov.b64 %0, {%1, %2};" : "=l"(dst) : "f"(lo), "f"(hi))
#define UNPK2(lo, hi, src) \
    asm("mov.b64 {%0, %1}, %2;" : "=f"(lo), "=f"(hi) : "l"(src))
#define FMA2(acc, a, b) \
    asm("fma.rn.f32x2 %0, %1, %2, %0;" : "+l"(acc) : "l"(a), "l"(b))

__global__ void __launch_bounds__(256) compose_kernel(const int* __restrict__ comp) {
    __shared__ int sinfo[T_ * 4];
    __shared__ __align__(16) float sa[D_];
    __shared__ __align__(16) float sb[512];   // b duplicated, natural layout
    __shared__ float pt[4][320];
    __shared__ float red[8];

    int b = blockIdx.x;
    int tid = threadIdx.x;
    float*  v   = g_vec   + (size_t)b * N_ * D_;
    __half* v16 = g_vec16 + (size_t)b * N_ * D_;

    for (int i = tid; i < T_ * 4; i += 256)
        sinfo[i] = comp[(size_t)b * T_ * 4 + i];
    __syncthreads();

    const int t  = tid & 63;
    const int g  = tid >> 6;
    const int j0 = g * 64;
    const int ftid = tid + (tid >> 2);
    // byte addresses for the 16B ld.shared.v2.u64 accesses
    const uint32_t bA = smem_to_u32(sb) + (uint32_t)(j0 + 4 * t) * 4;
    const uint32_t aA = smem_to_u32(sa) + (uint32_t)j0 * 4;

    int typ = sinfo[0], p = sinfo[1], l = sinfo[2], r = sinfo[3];
    float av = v[(size_t)l * D_ + tid];
    float bv = v[(size_t)r * D_ + tid];

    for (int ts = 0; ts < T_; ++ts) {
        int typ2 = 0, p2 = 0, l2 = 0, r2 = 0;
        float av2 = 0.f, bv2 = 0.f;
        if (ts + 1 < T_) {
            typ2 = sinfo[4 * ts + 4];
            p2   = sinfo[4 * ts + 5];
            l2   = sinfo[4 * ts + 6];
            r2   = sinfo[4 * ts + 7];
            av2 = v[(size_t)l2 * D_ + tid];
            bv2 = v[(size_t)r2 * D_ + tid];
        }

        float outv = 0.f;
        bool wrote = false;
        if (typ == 1) {
            outv = av;
            v[(size_t)p * D_ + tid] = outv;
            v16[(size_t)p * D_ + tid] = __float2half(outv);
            wrote = true;
        } else if (typ == 2) {
            sa[tid] = av;
            sb[tid] = bv;
            sb[tid + 256] = bv;
            __syncthreads();

            unsigned long long acc0 = 0ull, acc1 = 0ull, acc2 = 0ull, acc3 = 0ull;
            unsigned long long P0, P1, Q0, Q1, O0, O1, O2, pe0, pe1;
            float p0l, p0h, p1l, p1h, q0l, q0h, q1l, q1h;
            // preload window: pairs at m, m+2  (m = j0 + 4t)
            asm("ld.shared.v2.u64 {%0,%1}, [%2];" : "=l"(P0), "=l"(P1) : "r"(bA));
            UNPK2(p0l, p0h, P0);
            UNPK2(p1l, p1h, P1);
            PK2(O0, p0h, p1l);                 // pair at m+1
#pragma unroll
            for (int u = 0; u < 16; ++u) {
                asm("ld.shared.v2.u64 {%0,%1}, [%2];"
                    : "=l"(Q0), "=l"(Q1) : "r"(bA + 16u * (u + 1)));
                asm("ld.shared.v2.u64 {%0,%1}, [%2];"
                    : "=l"(pe0), "=l"(pe1) : "r"(aA + 16u * u));   // broadcast
                UNPK2(q0l, q0h, Q0);
                PK2(O1, p1h, q0l);             // pair at m+3
                FMA2(acc0, pe0, P0);
                FMA2(acc1, pe0, O0);
                FMA2(acc2, pe0, P1);
                FMA2(acc3, pe0, O1);
                UNPK2(q1l, q1h, Q1);
                PK2(O2, q0h, q1l);             // pair at m+5
                FMA2(acc0, pe1, P1);
                FMA2(acc1, pe1, O1);
                FMA2(acc2, pe1, Q0);
                FMA2(acc3, pe1, O2);
                P0 = Q0; P1 = Q1; O0 = O2; p1h = q1h;
            }
            float lo, hi, c0, c1, c2, c3;
            UNPK2(lo, hi, acc0); c0 = lo + hi;
            UNPK2(lo, hi, acc1); c1 = lo + hi;
            UNPK2(lo, hi, acc2); c2 = lo + hi;
            UNPK2(lo, hi, acc3); c3 = lo + hi;

            pt[g][5 * t + 0] = c0;
            pt[g][5 * t + 1] = c1;
            pt[g][5 * t + 2] = c2;
            pt[g][5 * t + 3] = c3;
            __syncthreads();

            float tot = pt[0][ftid] + pt[1][ftid] + pt[2][ftid] + pt[3][ftid];
            float ss = tot * tot;
#pragma unroll
            for (int o = 16; o > 0; o >>= 1)
                ss += __shfl_xor_sync(0xffffffffu, ss, o);
            if ((tid & 31) == 0) red[tid >> 5] = ss;
            __syncthreads();
            float tss = red[0] + red[1] + red[2] + red[3]
                      + red[4] + red[5] + red[6] + red[7];
            outv = tot / (sqrtf(tss) + EPS_);
            v[(size_t)p * D_ + tid] = outv;
            v16[(size_t)p * D_ + tid] = __float2half(outv);
            wrote = true;
            __syncthreads();
        }

        if (wrote && (ts + 1 < T_)) {
            if (l2 == p) av2 = outv;
            if (r2 == p) bv2 = outv;
        }
        typ = typ2; p = p2; l = l2; r = r2; av = av2; bv = bv2;
    }
}

// ---------------------------------------------------------------------------
// fp16 mma.sync m16n8k16 GEMM (R11 — best measured, unchanged).
// BM=128, BN=128, BK=32, 256 threads (8 warps: 4 along M x 2 along N).
// ---------------------------------------------------------------------------
#define GS_H 40                      // smem row stride in halfs (32 + 8 pad)
#define STAGE_H (256 * GS_H)         // halfs per stage

__device__ __forceinline__ void cp16(uint32_t dst, const void* src) {
    asm volatile("cp.async.ca.shared.global [%0], [%1], 16;"
                 :: "r"(dst), "l"(src) : "memory");
}
__device__ __forceinline__ void cp_commit() {
    asm volatile("cp.async.commit_group;" ::: "memory");
}
__device__ __forceinline__ void cp_wait0() {
    asm volatile("cp.async.wait_group 0;" ::: "memory");
}
__device__ __forceinline__ void mma_f16(float* d, const uint32_t* a,
                                        uint32_t b0, uint32_t b1) {
    asm volatile(
        "mma.sync.aligned.m16n8k16.row.col.f32.f16.f16.f32 "
        "{%0,%1,%2,%3}, {%4,%5,%6,%7}, {%8,%9}, {%0,%1,%2,%3};"
        : "+f"(d[0]), "+f"(d[1]), "+f"(d[2]), "+f"(d[3])
        : "r"(a[0]), "r"(a[1]), "r"(a[2]), "r"(a[3]), "r"(b0), "r"(b1));
}

extern __shared__ __half gm_smem[];

__global__ void __launch_bounds__(256, 2) gemm_mma_kernel(const float* __restrict__ bias,
                                                          float* __restrict__ out) {
    const __half* A = g_vec16;
    int tid = threadIdx.x;
    int wid = tid >> 5;
    int lane = tid & 31;
    int qr = lane >> 2;
    int c4 = lane & 3;
    int wm = wid & 3;
    int wn = wid >> 2;

    int n0 = blockIdx.x * 128;
    size_t m0 = (size_t)blockIdx.y * 128;

    int lrow = tid >> 1;
    int lseg = tid & 1;
    const __half* asrc = A + (m0 + lrow) * D_ + lseg * 16;
    const __half* bsrc = g_W16 + (size_t)(n0 + lrow) * D_ + lseg * 16;

    uint32_t smbase = smem_to_u32(gm_smem);
    uint32_t ldstA = smbase + (uint32_t)(lrow * GS_H + lseg * 16) * 2;
    uint32_t ldstB = ldstA + 128 * GS_H * 2;

#pragma unroll
    for (int q = 0; q < 2; ++q) {
        cp16(ldstA + q * 16, asrc + q * 8);
        cp16(ldstB + q * 16, bsrc + q * 8);
    }
    cp_commit();

    float acc[2][8][4];
#pragma unroll
    for (int mt = 0; mt < 2; ++mt)
#pragma unroll
        for (int nt = 0; nt < 8; ++nt)
#pragma unroll
            for (int w = 0; w < 4; ++w) acc[mt][nt][w] = 0.f;

    cp_wait0();
    __syncthreads();

    for (int bk = 0; bk < 8; ++bk) {
        int cur = bk & 1;
        if (bk < 7) {
            int nxt = cur ^ 1;
            uint32_t dA = ldstA + (uint32_t)(nxt * STAGE_H) * 2;
            uint32_t dB = ldstB + (uint32_t)(nxt * STAGE_H) * 2;
            const __half* as = asrc + (bk + 1) * 32;
            const __half* bs = bsrc + (bk + 1) * 32;
#pragma unroll
            for (int q = 0; q < 2; ++q) {
                cp16(dA + q * 16, as + q * 8);
                cp16(dB + q * 16, bs + q * 8);
            }
            cp_commit();
        }

        const __half* sA = gm_smem + cur * STAGE_H;
        const __half* sB = sA + 128 * GS_H;
        int ra = wm * 32 + qr;
        int nb = wn * 64 + qr;
#pragma unroll
        for (int sft = 0; sft < 2; ++sft) {
            int kb = 16 * sft + 2 * c4;
            uint32_t af[2][4];
#pragma unroll
            for (int mt = 0; mt < 2; ++mt) {
                int r0 = ra + mt * 16;
                af[mt][0] = *reinterpret_cast<const uint32_t*>(&sA[r0 * GS_H + kb]);
                af[mt][1] = *reinterpret_cast<const uint32_t*>(&sA[(r0 + 8) * GS_H + kb]);
                af[mt][2] = *reinterpret_cast<const uint32_t*>(&sA[r0 * GS_H + kb + 8]);
                af[mt][3] = *reinterpret_cast<const uint32_t*>(&sA[(r0 + 8) * GS_H + kb + 8]);
            }
#pragma unroll
            for (int nt = 0; nt < 8; ++nt) {
                int n = nb + nt * 8;
                uint32_t b0 = *reinterpret_cast<const uint32_t*>(&sB[n * GS_H + kb]);
                uint32_t b1 = *reinterpret_cast<const uint32_t*>(&sB[n * GS_H + kb + 8]);
                mma_f16(acc[0][nt], af[0], b0, b1);
                mma_f16(acc[1][nt], af[1], b0, b1);
            }
        }

        if (bk < 7) cp_wait0();
        __syncthreads();
    }

#pragma unroll
    for (int nt = 0; nt < 8; ++nt) {
        int col = n0 + wn * 64 + nt * 8 + 2 * c4;
        if (col >= C_) continue;
        bool c1ok = (col + 1) < C_;
        float b0v = bias[col];
        float b1v = c1ok ? bias[col + 1] : 0.f;
#pragma unroll
        for (int mt = 0; mt < 2; ++mt) {
            size_t m = m0 + wm * 32 + mt * 16 + qr;
            float* o0 = out + m * C_ + col;
            o0[0] = acc[mt][nt][0] + b0v;
            if (c1ok) o0[1] = acc[mt][nt][1] + b1v;
            float* o1 = out + (m + 8) * C_ + col;
            o1[0] = acc[mt][nt][2] + b0v;
            if (c1ok) o1[1] = acc[mt][nt][3] + b1v;
        }
    }
}

// ---------------------------------------------------------------------------
extern "C" void kernel_launch(void* const* d_in, const int* in_sizes, int n_in,
                              void* d_out, int out_size) {
    const int*   leaf_id = (const int*)d_in[1];    // (B,L,2) int32
    const int*   mask    = (const int*)d_in[2];    // (B,L)   int32
    const int*   comp    = (const int*)d_in[3];    // (B,T,4) int32
    const float* emb     = (const float*)d_in[4];  // (V,D)
    const float* W       = (const float*)d_in[5];  // (C,D)
    const float* bias    = (const float*)d_in[6];  // (C,)
    float* out = (float*)d_out;                    // (B,N,C)

    zero_kernel<<<2048, 256>>>();
    pack_w_kernel<<<512, 256>>>(W);
    embed_kernel<<<(B_ * L_ + 7) / 8, 256>>>(leaf_id, mask, emb);
    compose_kernel<<<B_, 256>>>(comp);

    static bool attr_set = false;
    if (!attr_set) {
        cudaFuncSetAttribute(gemm_mma_kernel,
                             cudaFuncAttributeMaxDynamicSharedMemorySize,
                             2 * STAGE_H * 2);
        attr_set = true;
    }
    dim3 grid(4, 1023);
    gemm_mma_kernel<<<grid, 256, 2 * STAGE_H * 2>>>(bias, out);
}

// round 15
// speedup vs baseline: 1.2584x; 1.0275x over previous
#include <cuda_runtime.h>
#include <cuda_fp16.h>
#include <math.h>
#include <stdint.h>

#define B_ 128
#define L_ 512
#define N_ 1023
#define T_ 511
#define D_ 256
#define C_ 511
#define EPS_ 1e-6f

// fp32 master copy (compose iterates on this) + fp16 mirror for the GEMM.
__device__ float  g_vec[(size_t)B_ * N_ * D_];     // 134 MB
__device__ __half g_vec16[(size_t)B_ * N_ * D_];   // 67 MB
__device__ __half g_W16[512 * 256];                // W fp16, zero-padded row 511

__device__ __forceinline__ uint32_t smem_to_u32(const void* p) {
    uint32_t a;
    asm("{ .reg .u64 t; cvta.to.shared.u64 t, %1; cvt.u32.u64 %0, t; }"
        : "=r"(a) : "l"(p));
    return a;
}

// ---------------------------------------------------------------------------
// Zero both node-vector buffers
// ---------------------------------------------------------------------------
__global__ void zero_kernel() {
    size_t t32 = (size_t)B_ * N_ * D_ / 4;
    float4* p = reinterpret_cast<float4*>(g_vec);
    float4 z = make_float4(0.f, 0.f, 0.f, 0.f);
    for (size_t i = (size_t)blockIdx.x * blockDim.x + threadIdx.x; i < t32;
         i += (size_t)gridDim.x * blockDim.x)
        p[i] = z;
    size_t t16 = (size_t)B_ * N_ * D_ / 8;
    uint4* q = reinterpret_cast<uint4*>(g_vec16);
    uint4 zz = make_uint4(0u, 0u, 0u, 0u);
    for (size_t i = (size_t)blockIdx.x * blockDim.x + threadIdx.x; i < t16;
         i += (size_t)gridDim.x * blockDim.x)
        q[i] = zz;
}

// ---------------------------------------------------------------------------
// Pack W (C,D) fp32 -> fp16, zero-padding to 512 rows.
// ---------------------------------------------------------------------------
__global__ void pack_w_kernel(const float* __restrict__ W) {
    int idx = blockIdx.x * 256 + threadIdx.x;
    int row = idx >> 8;
    int k   = idx & 255;
    g_W16[idx] = __float2half((row < C_) ? W[row * 256 + k] : 0.f);
}

// ---------------------------------------------------------------------------
// Scatter normalized embedding rows into g_vec + g_vec16. One warp per leaf.
// ---------------------------------------------------------------------------
__global__ void embed_kernel(const int* __restrict__ leaf_id,
                             const int* __restrict__ mask,
                             const float* __restrict__ emb) {
    int leaf = blockIdx.x * 8 + (threadIdx.x >> 5);
    int lane = threadIdx.x & 31;
    if (leaf >= B_ * L_) return;
    if (mask[leaf] == 0) return;
    int b = leaf / L_;
    int node = leaf_id[2 * leaf + 0];
    int vid  = leaf_id[2 * leaf + 1];
    if ((unsigned)node >= (unsigned)N_) return;
    const float4* src = reinterpret_cast<const float4*>(emb + (size_t)vid * D_);
    float4 v0 = src[lane];
    float4 v1 = src[lane + 32];
    float ss = v0.x * v0.x + v0.y * v0.y + v0.z * v0.z + v0.w * v0.w
             + v1.x * v1.x + v1.y * v1.y + v1.z * v1.z + v1.w * v1.w;
#pragma unroll
    for (int o = 16; o > 0; o >>= 1) ss += __shfl_xor_sync(0xffffffffu, ss, o);
    float inv = 1.f / (sqrtf(ss) + EPS_);
    v0.x *= inv; v0.y *= inv; v0.z *= inv; v0.w *= inv;
    v1.x *= inv; v1.y *= inv; v1.z *= inv; v1.w *= inv;
    size_t base = ((size_t)b * N_ + node) * D_;
    float4* dst = reinterpret_cast<float4*>(g_vec + base);
    dst[lane]      = v0;
    dst[lane + 32] = v1;
    __half2* dst16 = reinterpret_cast<__half2*>(g_vec16 + base);
    dst16[2 * lane + 0]  = __float22half2_rn(make_float2(v0.x, v0.y));
    dst16[2 * lane + 1]  = __float22half2_rn(make_float2(v0.z, v0.w));
    dst16[2 * lane + 64] = __float22half2_rn(make_float2(v1.x, v1.y));
    dst16[2 * lane + 65] = __float22half2_rn(make_float2(v1.z, v1.w));
}

// ---------------------------------------------------------------------------
// fp16 mma.sync m16n8k16 GEMM tile body (R11/R13 — best measured).
// BM=128, BN=128, BK=32, 256 threads (8 warps: 4 along M x 2 along N).
// ---------------------------------------------------------------------------
#define GS_H 40                      // smem row stride in halfs (32 + 8 pad)
#define STAGE_H (256 * GS_H)         // halfs per stage
#define GM_SMEM_BYTES (2 * STAGE_H * 2)   // 40960 B dynamic

__device__ __forceinline__ void cp16(uint32_t dst, const void* src) {
    asm volatile("cp.async.ca.shared.global [%0], [%1], 16;"
                 :: "r"(dst), "l"(src) : "memory");
}
__device__ __forceinline__ void cp_commit() {
    asm volatile("cp.async.commit_group;" ::: "memory");
}
__device__ __forceinline__ void cp_wait0() {
    asm volatile("cp.async.wait_group 0;" ::: "memory");
}
__device__ __forceinline__ void mma_f16(float* d, const uint32_t* a,
                                        uint32_t b0, uint32_t b1) {
    asm volatile(
        "mma.sync.aligned.m16n8k16.row.col.f32.f16.f16.f32 "
        "{%0,%1,%2,%3}, {%4,%5,%6,%7}, {%8,%9}, {%0,%1,%2,%3};"
        : "+f"(d[0]), "+f"(d[1]), "+f"(d[2]), "+f"(d[3])
        : "r"(a[0]), "r"(a[1]), "r"(a[2]), "r"(a[3]), "r"(b0), "r"(b1));
}

__device__ void gemm_tile(size_t m0, int n0,
                          const float* __restrict__ bias,
                          float* __restrict__ out) {
    extern __shared__ __half gm_smem[];
    const __half* A = g_vec16;
    int tid = threadIdx.x;
    int wid = tid >> 5;
    int lane = tid & 31;
    int qr = lane >> 2;
    int c4 = lane & 3;
    int wm = wid & 3;
    int wn = wid >> 2;

    int lrow = tid >> 1;
    int lseg = tid & 1;
    const __half* asrc = A + (m0 + lrow) * D_ + lseg * 16;
    const __half* bsrc = g_W16 + (size_t)(n0 + lrow) * D_ + lseg * 16;

    uint32_t smbase = smem_to_u32(gm_smem);
    uint32_t ldstA = smbase + (uint32_t)(lrow * GS_H + lseg * 16) * 2;
    uint32_t ldstB = ldstA + 128 * GS_H * 2;

#pragma unroll
    for (int q = 0; q < 2; ++q) {
        cp16(ldstA + q * 16, asrc + q * 8);
        cp16(ldstB + q * 16, bsrc + q * 8);
    }
    cp_commit();

    float acc[2][8][4];
#pragma unroll
    for (int mt = 0; mt < 2; ++mt)
#pragma unroll
        for (int nt = 0; nt < 8; ++nt)
#pragma unroll
            for (int w = 0; w < 4; ++w) acc[mt][nt][w] = 0.f;

    cp_wait0();
    __syncthreads();

    for (int bk = 0; bk < 8; ++bk) {
        int cur = bk & 1;
        if (bk < 7) {
            int nxt = cur ^ 1;
            uint32_t dA = ldstA + (uint32_t)(nxt * STAGE_H) * 2;
            uint32_t dB = ldstB + (uint32_t)(nxt * STAGE_H) * 2;
            const __half* as = asrc + (bk + 1) * 32;
            const __half* bs = bsrc + (bk + 1) * 32;
#pragma unroll
            for (int q = 0; q < 2; ++q) {
                cp16(dA + q * 16, as + q * 8);
                cp16(dB + q * 16, bs + q * 8);
            }
            cp_commit();
        }

        const __half* sA = gm_smem + cur * STAGE_H;
        const __half* sB = sA + 128 * GS_H;
        int ra = wm * 32 + qr;
        int nb = wn * 64 + qr;
#pragma unroll
        for (int sft = 0; sft < 2; ++sft) {
            int kb = 16 * sft + 2 * c4;
            uint32_t af[2][4];
#pragma unroll
            for (int mt = 0; mt < 2; ++mt) {
                int r0 = ra + mt * 16;
                af[mt][0] = *reinterpret_cast<const uint32_t*>(&sA[r0 * GS_H + kb]);
                af[mt][1] = *reinterpret_cast<const uint32_t*>(&sA[(r0 + 8) * GS_H + kb]);
                af[mt][2] = *reinterpret_cast<const uint32_t*>(&sA[r0 * GS_H + kb + 8]);
                af[mt][3] = *reinterpret_cast<const uint32_t*>(&sA[(r0 + 8) * GS_H + kb + 8]);
            }
#pragma unroll
            for (int nt = 0; nt < 8; ++nt) {
                int n = nb + nt * 8;
                uint32_t b0 = *reinterpret_cast<const uint32_t*>(&sB[n * GS_H + kb]);
                uint32_t b1 = *reinterpret_cast<const uint32_t*>(&sB[n * GS_H + kb + 8]);
                mma_f16(acc[0][nt], af[0], b0, b1);
                mma_f16(acc[1][nt], af[1], b0, b1);
            }
        }

        if (bk < 7) cp_wait0();
        __syncthreads();
    }

#pragma unroll
    for (int nt = 0; nt < 8; ++nt) {
        int col = n0 + wn * 64 + nt * 8 + 2 * c4;
        if (col >= C_) continue;
        bool c1ok = (col + 1) < C_;
        float b0v = bias[col];
        float b1v = c1ok ? bias[col + 1] : 0.f;
#pragma unroll
        for (int mt = 0; mt < 2; ++mt) {
            size_t m = m0 + wm * 32 + mt * 16 + qr;
            float* o0 = out + m * C_ + col;
            o0[0] = acc[mt][nt][0] + b0v;
            if (c1ok) o0[1] = acc[mt][nt][1] + b1v;
            float* o1 = out + (m + 8) * C_ + col;
            o1[0] = acc[mt][nt][2] + b0v;
            if (c1ok) o1[1] = acc[mt][nt][3] + b1v;
        }
    }
}

// ---------------------------------------------------------------------------
// Compose body (R13 f32x2 version — best measured), one block per batch.
// ---------------------------------------------------------------------------
#define PK2(dst, lo, hi) \
    asm("mov.b64 %0, {%1, %2};" : "=l"(dst) : "f"(lo), "f"(hi))
#define UNPK2(lo, hi, src) \
    asm("mov.b64 {%0, %1}, %2;" : "=f"(lo), "=f"(hi) : "l"(src))
#define FMA2(acc, a, b) \
    asm("fma.rn.f32x2 %0, %1, %2, %0;" : "+l"(acc) : "l"(a), "l"(b))

__device__ void compose_body(int b, const int* __restrict__ comp) {
    __shared__ int sinfo[T_ * 4];
    __shared__ __align__(16) float sa[D_];
    __shared__ __align__(16) float sb[512];
    __shared__ float pt[4][320];
    __shared__ float red[8];

    int tid = threadIdx.x;
    float*  v   = g_vec   + (size_t)b * N_ * D_;
    __half* v16 = g_vec16 + (size_t)b * N_ * D_;

    for (int i = tid; i < T_ * 4; i += 256)
        sinfo[i] = comp[(size_t)b * T_ * 4 + i];
    __syncthreads();

    const int t  = tid & 63;
    const int g  = tid >> 6;
    const int j0 = g * 64;
    const int ftid = tid + (tid >> 2);
    const uint32_t bA = smem_to_u32(sb) + (uint32_t)(j0 + 4 * t) * 4;
    const uint32_t aA = smem_to_u32(sa) + (uint32_t)j0 * 4;

    int typ = sinfo[0], p = sinfo[1], l = sinfo[2], r = sinfo[3];
    float av = v[(size_t)l * D_ + tid];
    float bv = v[(size_t)r * D_ + tid];

    for (int ts = 0; ts < T_; ++ts) {
        int typ2 = 0, p2 = 0, l2 = 0, r2 = 0;
        float av2 = 0.f, bv2 = 0.f;
        if (ts + 1 < T_) {
            typ2 = sinfo[4 * ts + 4];
            p2   = sinfo[4 * ts + 5];
            l2   = sinfo[4 * ts + 6];
            r2   = sinfo[4 * ts + 7];
            av2 = v[(size_t)l2 * D_ + tid];
            bv2 = v[(size_t)r2 * D_ + tid];
        }

        float outv = 0.f;
        bool wrote = false;
        if (typ == 1) {
            outv = av;
            v[(size_t)p * D_ + tid] = outv;
            v16[(size_t)p * D_ + tid] = __float2half(outv);
            wrote = true;
        } else if (typ == 2) {
            sa[tid] = av;
            sb[tid] = bv;
            sb[tid + 256] = bv;
            __syncthreads();

            unsigned long long acc0 = 0ull, acc1 = 0ull, acc2 = 0ull, acc3 = 0ull;
            unsigned long long P0, P1, Q0, Q1, O0, O1, O2, pe0, pe1;
            float p0l, p0h, p1l, p1h, q0l, q0h, q1l, q1h;
            asm("ld.shared.v2.u64 {%0,%1}, [%2];" : "=l"(P0), "=l"(P1) : "r"(bA));
            UNPK2(p0l, p0h, P0);
            UNPK2(p1l, p1h, P1);
            PK2(O0, p0h, p1l);
#pragma unroll
            for (int u = 0; u < 16; ++u) {
                asm("ld.shared.v2.u64 {%0,%1}, [%2];"
                    : "=l"(Q0), "=l"(Q1) : "r"(bA + 16u * (u + 1)));
                asm("ld.shared.v2.u64 {%0,%1}, [%2];"
                    : "=l"(pe0), "=l"(pe1) : "r"(aA + 16u * u));
                UNPK2(q0l, q0h, Q0);
                PK2(O1, p1h, q0l);
                FMA2(acc0, pe0, P0);
                FMA2(acc1, pe0, O0);
                FMA2(acc2, pe0, P1);
                FMA2(acc3, pe0, O1);
                UNPK2(q1l, q1h, Q1);
                PK2(O2, q0h, q1l);
                FMA2(acc0, pe1, P1);
                FMA2(acc1, pe1, O1);
                FMA2(acc2, pe1, Q0);
                FMA2(acc3, pe1, O2);
                P0 = Q0; P1 = Q1; O0 = O2; p1h = q1h;
            }
            float lo, hi, c0, c1, c2, c3;
            UNPK2(lo, hi, acc0); c0 = lo + hi;
            UNPK2(lo, hi, acc1); c1 = lo + hi;
            UNPK2(lo, hi, acc2); c2 = lo + hi;
            UNPK2(lo, hi, acc3); c3 = lo + hi;

            pt[g][5 * t + 0] = c0;
            pt[g][5 * t + 1] = c1;
            pt[g][5 * t + 2] = c2;
            pt[g][5 * t + 3] = c3;
            __syncthreads();

            float tot = pt[0][ftid] + pt[1][ftid] + pt[2][ftid] + pt[3][ftid];
            float ss = tot * tot;
#pragma unroll
            for (int o = 16; o > 0; o >>= 1)
                ss += __shfl_xor_sync(0xffffffffu, ss, o);
            if ((tid & 31) == 0) red[tid >> 5] = ss;
            __syncthreads();
            float tss = red[0] + red[1] + red[2] + red[3]
                      + red[4] + red[5] + red[6] + red[7];
            outv = tot / (sqrtf(tss) + EPS_);
            v[(size_t)p * D_ + tid] = outv;
            v16[(size_t)p * D_ + tid] = __float2half(outv);
            wrote = true;
            __syncthreads();
        }

        if (wrote && (ts + 1 < T_)) {
            if (l2 == p) av2 = outv;
            if (r2 == p) bv2 = outv;
        }
        typ = typ2; p = p2; l = l2; r = r2; av = av2; bv = bv2;
    }
}

// ---------------------------------------------------------------------------
// Fused launch: blocks 0..127 run compose (one batch each, critical path,
// dispatched first); blocks 128..2175 run the LEAF-half GEMM (rows [0,512)
// per batch — final after embed, independent of compose, since every
// composition writes only parent nodes in [512,1023) or is a no-op).
// ---------------------------------------------------------------------------
__global__ void __launch_bounds__(256, 2) fused_compose_leafgemm(
    const int* __restrict__ comp,
    const float* __restrict__ bias,
    float* __restrict__ out) {
    if (blockIdx.x < B_) {
        compose_body(blockIdx.x, comp);
    } else {
        int gidx = blockIdx.x - B_;        // 0..2047
        int n0 = (gidx & 3) * 128;
        int mt = gidx >> 2;                // 0..511
        int b  = mt >> 2;
        int ty = mt & 3;
        size_t m0 = (size_t)b * N_ + (size_t)ty * 128;   // leaf rows [0,512)
        gemm_tile(m0, n0, bias, out);
    }
}

// ---------------------------------------------------------------------------
// Internal-node GEMM: rows [512,1023) per batch, 4 tiles (last tile starts at
// 895 so it ends exactly at row 1022; row 895 double-written with identical
// values — benign).
// ---------------------------------------------------------------------------
__global__ void __launch_bounds__(256, 2) gemm_internal_kernel(
    const float* __restrict__ bias,
    float* __restrict__ out) {
    int n0 = blockIdx.x * 128;
    int b  = blockIdx.y >> 2;
    int ty = blockIdx.y & 3;
    size_t m0 = (size_t)b * N_ + (size_t)((ty < 3) ? 512 + ty * 128 : 895);
    gemm_tile(m0, n0, bias, out);
}

// ---------------------------------------------------------------------------
extern "C" void kernel_launch(void* const* d_in, const int* in_sizes, int n_in,
                              void* d_out, int out_size) {
    const int*   leaf_id = (const int*)d_in[1];    // (B,L,2) int32
    const int*   mask    = (const int*)d_in[2];    // (B,L)   int32
    const int*   comp    = (const int*)d_in[3];    // (B,T,4) int32
    const float* emb     = (const float*)d_in[4];  // (V,D)
    const float* W       = (const float*)d_in[5];  // (C,D)
    const float* bias    = (const float*)d_in[6];  // (C,)
    float* out = (float*)d_out;                    // (B,N,C)

    // Opt in to >48KB (static + dynamic) shared memory for the GEMM-carrying
    // kernels. Host-side attribute set, performed once (proven pattern).
    static bool attr_set = false;
    if (!attr_set) {
        cudaFuncSetAttribute(fused_compose_leafgemm,
                             cudaFuncAttributeMaxDynamicSharedMemorySize,
                             GM_SMEM_BYTES);
        cudaFuncSetAttribute(gemm_internal_kernel,
                             cudaFuncAttributeMaxDynamicSharedMemorySize,
                             GM_SMEM_BYTES);
        attr_set = true;
    }

    zero_kernel<<<2048, 256>>>();
    pack_w_kernel<<<512, 256>>>(W);
    embed_kernel<<<(B_ * L_ + 7) / 8, 256>>>(leaf_id, mask, emb);

    // compose (128 blocks, critical path) + leaf-half GEMM (2048 blocks)
    fused_compose_leafgemm<<<B_ + 2048, 256, GM_SMEM_BYTES>>>(comp, bias, out);

    // internal-node half of the GEMM (depends on compose)
    dim3 gi(4, 512);
    gemm_internal_kernel<<<gi, 256, GM_SMEM_BYTES>>>(bias, out);
}

// round 16
// speedup vs baseline: 1.4709x; 1.1689x over previous
#include <cuda_runtime.h>
#include <cuda_fp16.h>
#include <math.h>
#include <stdint.h>

#define B_ 128
#define L_ 512
#define N_ 1023
#define T_ 511
#define D_ 256
#define C_ 511
#define EPS_ 1e-6f

// fp32 master copy (compose iterates on this) + fp16 mirror for the GEMM.
__device__ float  g_vec[(size_t)B_ * N_ * D_];     // 134 MB
__device__ __half g_vec16[(size_t)B_ * N_ * D_];   // 67 MB
__device__ __half g_W16[512 * 256];                // W fp16, zero-padded row 511

__device__ __forceinline__ uint32_t smem_to_u32(const void* p) {
    uint32_t a;
    asm("{ .reg .u64 t; cvta.to.shared.u64 t, %1; cvt.u32.u64 %0, t; }"
        : "=r"(a) : "l"(p));
    return a;
}

// ---------------------------------------------------------------------------
// ONE dependency-free init kernel:
//  blocks [0, 8192):      leaf rows (b, i<512) — dense embed (leaf node id is
//                         the identity map per setup), zeros when masked
//  blocks [8192, 16368):  internal rows (b, 512..1022) — zero fp32 + fp16
//  blocks [16368, 16880): pack W fp32 -> fp16 (512-row zero-padded)
// ---------------------------------------------------------------------------
__global__ void __launch_bounds__(256) init_kernel(const int* __restrict__ leaf_id,
                                                   const int* __restrict__ mask,
                                                   const float* __restrict__ emb,
                                                   const float* __restrict__ W) {
    int blk = blockIdx.x;
    int w    = threadIdx.x >> 5;
    int lane = threadIdx.x & 31;

    if (blk < 8192) {
        int idx = blk * 8 + w;            // 0..65535 = b*512 + i
        int b = idx >> 9;
        int i = idx & 511;
        size_t base = ((size_t)b * N_ + i) * D_;
        float4*  dst   = reinterpret_cast<float4*>(g_vec + base);
        uint4*   dst16 = reinterpret_cast<uint4*>(g_vec16 + base);
        if (mask[idx] == 0) {
            float4 z = make_float4(0.f, 0.f, 0.f, 0.f);
            dst[lane] = z; dst[lane + 32] = z;
            dst16[lane] = make_uint4(0u, 0u, 0u, 0u);   // 32 lanes x 16B = 512B
        } else {
            int vid = leaf_id[2 * idx + 1];
            const float4* src = reinterpret_cast<const float4*>(emb + (size_t)vid * D_);
            float4 v0 = src[lane];
            float4 v1 = src[lane + 32];
            float ss = v0.x * v0.x + v0.y * v0.y + v0.z * v0.z + v0.w * v0.w
                     + v1.x * v1.x + v1.y * v1.y + v1.z * v1.z + v1.w * v1.w;
#pragma unroll
            for (int o = 16; o > 0; o >>= 1) ss += __shfl_xor_sync(0xffffffffu, ss, o);
            float inv = 1.f / (sqrtf(ss) + EPS_);
            v0.x *= inv; v0.y *= inv; v0.z *= inv; v0.w *= inv;
            v1.x *= inv; v1.y *= inv; v1.z *= inv; v1.w *= inv;
            dst[lane]      = v0;
            dst[lane + 32] = v1;
            __half2 h[4];
            h[0] = __float22half2_rn(make_float2(v0.x, v0.y));
            h[1] = __float22half2_rn(make_float2(v0.z, v0.w));
            h[2] = __float22half2_rn(make_float2(v1.x, v1.y));
            h[3] = __float22half2_rn(make_float2(v1.z, v1.w));
            __half2* d2 = reinterpret_cast<__half2*>(g_vec16 + base);
            d2[2 * lane + 0]  = h[0];
            d2[2 * lane + 1]  = h[1];
            d2[2 * lane + 64] = h[2];
            d2[2 * lane + 65] = h[3];
        }
    } else if (blk < 16368) {
        int idx = (blk - 8192) * 8 + w;   // 0..65407 (need 128*511 = 65408)
        if (idx < 128 * 511) {
            int b   = idx / 511;
            int row = 512 + idx % 511;
            size_t base = ((size_t)b * N_ + row) * D_;
            float4 z = make_float4(0.f, 0.f, 0.f, 0.f);
            float4* dst = reinterpret_cast<float4*>(g_vec + base);
            dst[lane] = z; dst[lane + 32] = z;
            reinterpret_cast<uint4*>(g_vec16 + base)[lane] = make_uint4(0u, 0u, 0u, 0u);
        }
    } else {
        int idx = (blk - 16368) * 256 + threadIdx.x;   // 0..131071
        int row = idx >> 8;
        int k   = idx & 255;
        g_W16[idx] = __float2half((row < C_) ? W[row * 256 + k] : 0.f);
    }
}

// ---------------------------------------------------------------------------
// fp16 mma.sync m16n8k16 GEMM tile body (R11/R13 — best measured).
// ---------------------------------------------------------------------------
#define GS_H 40                      // smem row stride in halfs (32 + 8 pad)
#define STAGE_H (256 * GS_H)         // halfs per stage
#define GM_SMEM_BYTES (2 * STAGE_H * 2)   // 40960 B dynamic

__device__ __forceinline__ void cp16(uint32_t dst, const void* src) {
    asm volatile("cp.async.ca.shared.global [%0], [%1], 16;"
                 :: "r"(dst), "l"(src) : "memory");
}
__device__ __forceinline__ void cp_commit() {
    asm volatile("cp.async.commit_group;" ::: "memory");
}
__device__ __forceinline__ void cp_wait0() {
    asm volatile("cp.async.wait_group 0;" ::: "memory");
}
__device__ __forceinline__ void mma_f16(float* d, const uint32_t* a,
                                        uint32_t b0, uint32_t b1) {
    asm volatile(
        "mma.sync.aligned.m16n8k16.row.col.f32.f16.f16.f32 "
        "{%0,%1,%2,%3}, {%4,%5,%6,%7}, {%8,%9}, {%0,%1,%2,%3};"
        : "+f"(d[0]), "+f"(d[1]), "+f"(d[2]), "+f"(d[3])
        : "r"(a[0]), "r"(a[1]), "r"(a[2]), "r"(a[3]), "r"(b0), "r"(b1));
}

__device__ void gemm_tile(size_t m0, int n0,
                          const float* __restrict__ bias,
                          float* __restrict__ out) {
    extern __shared__ __half gm_smem[];
    const __half* A = g_vec16;
    int tid = threadIdx.x;
    int wid = tid >> 5;
    int lane = tid & 31;
    int qr = lane >> 2;
    int c4 = lane & 3;
    int wm = wid & 3;
    int wn = wid >> 2;

    int lrow = tid >> 1;
    int lseg = tid & 1;
    const __half* asrc = A + (m0 + lrow) * D_ + lseg * 16;
    const __half* bsrc = g_W16 + (size_t)(n0 + lrow) * D_ + lseg * 16;

    uint32_t smbase = smem_to_u32(gm_smem);
    uint32_t ldstA = smbase + (uint32_t)(lrow * GS_H + lseg * 16) * 2;
    uint32_t ldstB = ldstA + 128 * GS_H * 2;

#pragma unroll
    for (int q = 0; q < 2; ++q) {
        cp16(ldstA + q * 16, asrc + q * 8);
        cp16(ldstB + q * 16, bsrc + q * 8);
    }
    cp_commit();

    float acc[2][8][4];
#pragma unroll
    for (int mt = 0; mt < 2; ++mt)
#pragma unroll
        for (int nt = 0; nt < 8; ++nt)
#pragma unroll
            for (int u = 0; u < 4; ++u) acc[mt][nt][u] = 0.f;

    cp_wait0();
    __syncthreads();

    for (int bk = 0; bk < 8; ++bk) {
        int cur = bk & 1;
        if (bk < 7) {
            int nxt = cur ^ 1;
            uint32_t dA = ldstA + (uint32_t)(nxt * STAGE_H) * 2;
            uint32_t dB = ldstB + (uint32_t)(nxt * STAGE_H) * 2;
            const __half* as = asrc + (bk + 1) * 32;
            const __half* bs = bsrc + (bk + 1) * 32;
#pragma unroll
            for (int q = 0; q < 2; ++q) {
                cp16(dA + q * 16, as + q * 8);
                cp16(dB + q * 16, bs + q * 8);
            }
            cp_commit();
        }

        const __half* sA = gm_smem + cur * STAGE_H;
        const __half* sB = sA + 128 * GS_H;
        int ra = wm * 32 + qr;
        int nb = wn * 64 + qr;
#pragma unroll
        for (int sft = 0; sft < 2; ++sft) {
            int kb = 16 * sft + 2 * c4;
            uint32_t af[2][4];
#pragma unroll
            for (int mt = 0; mt < 2; ++mt) {
                int r0 = ra + mt * 16;
                af[mt][0] = *reinterpret_cast<const uint32_t*>(&sA[r0 * GS_H + kb]);
                af[mt][1] = *reinterpret_cast<const uint32_t*>(&sA[(r0 + 8) * GS_H + kb]);
                af[mt][2] = *reinterpret_cast<const uint32_t*>(&sA[r0 * GS_H + kb + 8]);
                af[mt][3] = *reinterpret_cast<const uint32_t*>(&sA[(r0 + 8) * GS_H + kb + 8]);
            }
#pragma unroll
            for (int nt = 0; nt < 8; ++nt) {
                int n = nb + nt * 8;
                uint32_t b0 = *reinterpret_cast<const uint32_t*>(&sB[n * GS_H + kb]);
                uint32_t b1 = *reinterpret_cast<const uint32_t*>(&sB[n * GS_H + kb + 8]);
                mma_f16(acc[0][nt], af[0], b0, b1);
                mma_f16(acc[1][nt], af[1], b0, b1);
            }
        }

        if (bk < 7) cp_wait0();
        __syncthreads();
    }

#pragma unroll
    for (int nt = 0; nt < 8; ++nt) {
        int col = n0 + wn * 64 + nt * 8 + 2 * c4;
        if (col >= C_) continue;
        bool c1ok = (col + 1) < C_;
        float b0v = bias[col];
        float b1v = c1ok ? bias[col + 1] : 0.f;
#pragma unroll
        for (int mt = 0; mt < 2; ++mt) {
            size_t m = m0 + wm * 32 + mt * 16 + qr;
            float* o0 = out + m * C_ + col;
            o0[0] = acc[mt][nt][0] + b0v;
            if (c1ok) o0[1] = acc[mt][nt][1] + b1v;
            float* o1 = out + (m + 8) * C_ + col;
            o1[0] = acc[mt][nt][2] + b0v;
            if (c1ok) o1[1] = acc[mt][nt][3] + b1v;
        }
    }
}

// ---------------------------------------------------------------------------
// Compose body (R13 f32x2) + type-0 step compaction + reduced barriers.
// ---------------------------------------------------------------------------
#define PK2(dst, lo, hi) \
    asm("mov.b64 %0, {%1, %2};" : "=l"(dst) : "f"(lo), "f"(hi))
#define UNPK2(lo, hi, src) \
    asm("mov.b64 {%0, %1}, %2;" : "=f"(lo), "=f"(hi) : "l"(src))
#define FMA2(acc, a, b) \
    asm("fma.rn.f32x2 %0, %1, %2, %0;" : "+l"(acc) : "l"(a), "l"(b))

__device__ void compose_body(int b, const int* __restrict__ comp) {
    __shared__ int sinfo[T_ * 4];        // compacted (type>0 only)
    __shared__ __align__(16) float sa[D_];
    __shared__ __align__(16) float sb[512];
    __shared__ float pt[4][320];
    __shared__ float red[8];
    __shared__ int warp_tot[8];
    __shared__ int s_base;

    int tid = threadIdx.x;
    float*  v   = g_vec   + (size_t)b * N_ * D_;
    __half* v16 = g_vec16 + (size_t)b * N_ * D_;
    const int* src = comp + (size_t)b * T_ * 4;

    // ---- compact out type-0 steps (ballot scan, order-preserving)
    if (tid == 0) s_base = 0;
    __syncthreads();
#pragma unroll 1
    for (int pass = 0; pass < 2; ++pass) {
        int e = pass * 256 + tid;
        int t0 = 0, t1 = 0, t2 = 0, t3 = 0;
        bool keep = false;
        if (e < T_) {
            t0 = src[4 * e]; t1 = src[4 * e + 1];
            t2 = src[4 * e + 2]; t3 = src[4 * e + 3];
            keep = (t0 > 0);
        }
        unsigned m = __ballot_sync(0xffffffffu, keep);
        int lane = tid & 31, w = tid >> 5;
        int lpre = __popc(m & ((1u << lane) - 1u));
        if (lane == 0) warp_tot[w] = __popc(m);
        __syncthreads();
        int woff = 0;
        for (int i = 0; i < w; ++i) woff += warp_tot[i];
        int base = s_base;
        if (keep) {
            int d = base + woff + lpre;
            sinfo[4 * d + 0] = t0; sinfo[4 * d + 1] = t1;
            sinfo[4 * d + 2] = t2; sinfo[4 * d + 3] = t3;
        }
        __syncthreads();
        if (tid == 0) {
            int tot = 0;
            for (int i = 0; i < 8; ++i) tot += warp_tot[i];
            s_base = base + tot;
        }
        __syncthreads();
    }
    const int Tc = s_base;
    __syncthreads();
    if (Tc == 0) return;

    const int t  = tid & 63;
    const int g  = tid >> 6;
    const int j0 = g * 64;
    const int ftid = tid + (tid >> 2);
    const uint32_t bA = smem_to_u32(sb) + (uint32_t)(j0 + 4 * t) * 4;
    const uint32_t aA = smem_to_u32(sa) + (uint32_t)j0 * 4;

    int typ = sinfo[0], p = sinfo[1], l = sinfo[2], r = sinfo[3];
    float av = v[(size_t)l * D_ + tid];
    float bv = v[(size_t)r * D_ + tid];

    for (int ts = 0; ts < Tc; ++ts) {
        int typ2 = 0, p2 = 0, l2 = 0, r2 = 0;
        float av2 = 0.f, bv2 = 0.f;
        if (ts + 1 < Tc) {
            typ2 = sinfo[4 * ts + 4];
            p2   = sinfo[4 * ts + 5];
            l2   = sinfo[4 * ts + 6];
            r2   = sinfo[4 * ts + 7];
            av2 = v[(size_t)l2 * D_ + tid];
            bv2 = v[(size_t)r2 * D_ + tid];
        }

        float outv;
        if (typ == 1) {
            outv = av;
            v[(size_t)p * D_ + tid] = outv;
            v16[(size_t)p * D_ + tid] = __float2half(outv);
        } else {   // typ == 2
            sa[tid] = av;
            sb[tid] = bv;
            sb[tid + 256] = bv;
            __syncthreads();

            unsigned long long acc0 = 0ull, acc1 = 0ull, acc2 = 0ull, acc3 = 0ull;
            unsigned long long P0, P1, Q0, Q1, O0, O1, O2, pe0, pe1;
            float p0l, p0h, p1l, p1h, q0l, q0h, q1l, q1h;
            asm("ld.shared.v2.u64 {%0,%1}, [%2];" : "=l"(P0), "=l"(P1) : "r"(bA));
            UNPK2(p0l, p0h, P0);
            UNPK2(p1l, p1h, P1);
            PK2(O0, p0h, p1l);
#pragma unroll
            for (int u = 0; u < 16; ++u) {
                asm("ld.shared.v2.u64 {%0,%1}, [%2];"
                    : "=l"(Q0), "=l"(Q1) : "r"(bA + 16u * (u + 1)));
                asm("ld.shared.v2.u64 {%0,%1}, [%2];"
                    : "=l"(pe0), "=l"(pe1) : "r"(aA + 16u * u));
                UNPK2(q0l, q0h, Q0);
                PK2(O1, p1h, q0l);
                FMA2(acc0, pe0, P0);
                FMA2(acc1, pe0, O0);
                FMA2(acc2, pe0, P1);
                FMA2(acc3, pe0, O1);
                UNPK2(q1l, q1h, Q1);
                PK2(O2, q0h, q1l);
                FMA2(acc0, pe1, P1);
                FMA2(acc1, pe1, O1);
                FMA2(acc2, pe1, Q0);
                FMA2(acc3, pe1, O2);
                P0 = Q0; P1 = Q1; O0 = O2; p1h = q1h;
            }
            float lo, hi, c0, c1, c2, c3;
            UNPK2(lo, hi, acc0); c0 = lo + hi;
            UNPK2(lo, hi, acc1); c1 = lo + hi;
            UNPK2(lo, hi, acc2); c2 = lo + hi;
            UNPK2(lo, hi, acc3); c3 = lo + hi;

            pt[g][5 * t + 0] = c0;
            pt[g][5 * t + 1] = c1;
            pt[g][5 * t + 2] = c2;
            pt[g][5 * t + 3] = c3;
            __syncthreads();

            float tot = pt[0][ftid] + pt[1][ftid] + pt[2][ftid] + pt[3][ftid];
            float ss = tot * tot;
#pragma unroll
            for (int o = 16; o > 0; o >>= 1)
                ss += __shfl_xor_sync(0xffffffffu, ss, o);
            if ((tid & 31) == 0) red[tid >> 5] = ss;
            __syncthreads();
            float tss = red[0] + red[1] + red[2] + red[3]
                      + red[4] + red[5] + red[6] + red[7];
            outv = tot / (sqrtf(tss) + EPS_);
            v[(size_t)p * D_ + tid] = outv;
            v16[(size_t)p * D_ + tid] = __float2half(outv);
            // no trailing sync: next step's smem writes (sa/sb) are ordered by
            // the next stage-sync; pt/red writes occur after later barriers.
        }

        if (ts + 1 < Tc) {
            if (l2 == p) av2 = outv;
            if (r2 == p) bv2 = outv;
        }
        typ = typ2; p = p2; l = l2; r = r2; av = av2; bv = bv2;
    }
}

// ---------------------------------------------------------------------------
// Fused launch: blocks 0..127 run compose; blocks 128..2175 run the LEAF-half
// GEMM (rows [0,512) final after init since parents are all >= 512).
// ---------------------------------------------------------------------------
__global__ void __launch_bounds__(256, 2) fused_compose_leafgemm(
    const int* __restrict__ comp,
    const float* __restrict__ bias,
    float* __restrict__ out) {
    if (blockIdx.x < B_) {
        compose_body(blockIdx.x, comp);
    } else {
        int gidx = blockIdx.x - B_;        // 0..2047
        int n0 = (gidx & 3) * 128;
        int mt = gidx >> 2;                // 0..511
        int b  = mt >> 2;
        int ty = mt & 3;
        size_t m0 = (size_t)b * N_ + (size_t)ty * 128;   // leaf rows [0,512)
        gemm_tile(m0, n0, bias, out);
    }
}

// ---------------------------------------------------------------------------
// Internal-node GEMM: rows [512,1023) per batch, 4 tiles (last tile shifted
// to row 895; overlap rows double-written with identical values — benign).
// ---------------------------------------------------------------------------
__global__ void __launch_bounds__(256, 2) gemm_internal_kernel(
    const float* __restrict__ bias,
    float* __restrict__ out) {
    int n0 = blockIdx.x * 128;
    int b  = blockIdx.y >> 2;
    int ty = blockIdx.y & 3;
    size_t m0 = (size_t)b * N_ + (size_t)((ty < 3) ? 512 + ty * 128 : 895);
    gemm_tile(m0, n0, bias, out);
}

// ---------------------------------------------------------------------------
extern "C" void kernel_launch(void* const* d_in, const int* in_sizes, int n_in,
                              void* d_out, int out_size) {
    const int*   leaf_id = (const int*)d_in[1];    // (B,L,2) int32
    const int*   mask    = (const int*)d_in[2];    // (B,L)   int32
    const int*   comp    = (const int*)d_in[3];    // (B,T,4) int32
    const float* emb     = (const float*)d_in[4];  // (V,D)
    const float* W       = (const float*)d_in[5];  // (C,D)
    const float* bias    = (const float*)d_in[6];  // (C,)
    float* out = (float*)d_out;                    // (B,N,C)

    static bool attr_set = false;
    if (!attr_set) {
        cudaFuncSetAttribute(fused_compose_leafgemm,
                             cudaFuncAttributeMaxDynamicSharedMemorySize,
                             GM_SMEM_BYTES);
        cudaFuncSetAttribute(gemm_internal_kernel,
                             cudaFuncAttributeMaxDynamicSharedMemorySize,
                             GM_SMEM_BYTES);
        attr_set = true;
    }

    // one dependency-free prologue launch (embed leaves + zero internal + pack W)
    init_kernel<<<16880, 256>>>(leaf_id, mask, emb, W);

    // compose (128 blocks, critical path) + leaf-half GEMM (2048 blocks)
    fused_compose_leafgemm<<<B_ + 2048, 256, GM_SMEM_BYTES>>>(comp, bias, out);

    // internal-node half of the GEMM (depends on compose)
    dim3 gi(4, 512);
    gemm_internal_kernel<<<gi, 256, GM_SMEM_BYTES>>>(bias, out);
}

// round 17
// speedup vs baseline: 1.5187x; 1.0325x over previous
#include <cuda_runtime.h>
#include <cuda_fp16.h>
#include <math.h>
#include <stdint.h>

#define B_ 128
#define L_ 512
#define N_ 1023
#define T_ 511
#define D_ 256
#define C_ 511
#define EPS_ 1e-6f

// fp32 master copy (compose iterates on this) + fp16 mirror for the GEMM.
__device__ float  g_vec[(size_t)B_ * N_ * D_];     // 134 MB
__device__ __half g_vec16[(size_t)B_ * N_ * D_];   // 67 MB
__device__ __half g_W16[512 * 256];                // W fp16, zero-padded row 511
__device__ int    g_done[B_];                      // per-batch compose flags

__device__ __forceinline__ uint32_t smem_to_u32(const void* p) {
    uint32_t a;
    asm("{ .reg .u64 t; cvta.to.shared.u64 t, %1; cvt.u32.u64 %0, t; }"
        : "=r"(a) : "l"(p));
    return a;
}

// ---------------------------------------------------------------------------
// ONE dependency-free init kernel:
//  blocks [0, 8192):      leaf rows (b, i<512) — dense embed (leaf node id is
//                         the identity map per setup), zeros when masked
//  blocks [8192, 16368):  internal rows (b, 512..1022) — zero fp32 + fp16
//  blocks [16368, 16880): pack W fp32 -> fp16; block 16368 also zeroes flags
// ---------------------------------------------------------------------------
__global__ void __launch_bounds__(256) init_kernel(const int* __restrict__ leaf_id,
                                                   const int* __restrict__ mask,
                                                   const float* __restrict__ emb,
                                                   const float* __restrict__ W) {
    int blk = blockIdx.x;
    int w    = threadIdx.x >> 5;
    int lane = threadIdx.x & 31;

    if (blk < 8192) {
        int idx = blk * 8 + w;            // 0..65535 = b*512 + i
        int b = idx >> 9;
        int i = idx & 511;
        size_t base = ((size_t)b * N_ + i) * D_;
        float4*  dst   = reinterpret_cast<float4*>(g_vec + base);
        uint4*   dst16 = reinterpret_cast<uint4*>(g_vec16 + base);
        if (mask[idx] == 0) {
            float4 z = make_float4(0.f, 0.f, 0.f, 0.f);
            dst[lane] = z; dst[lane + 32] = z;
            dst16[lane] = make_uint4(0u, 0u, 0u, 0u);
        } else {
            int vid = leaf_id[2 * idx + 1];
            const float4* src = reinterpret_cast<const float4*>(emb + (size_t)vid * D_);
            float4 v0 = src[lane];
            float4 v1 = src[lane + 32];
            float ss = v0.x * v0.x + v0.y * v0.y + v0.z * v0.z + v0.w * v0.w
                     + v1.x * v1.x + v1.y * v1.y + v1.z * v1.z + v1.w * v1.w;
#pragma unroll
            for (int o = 16; o > 0; o >>= 1) ss += __shfl_xor_sync(0xffffffffu, ss, o);
            float inv = 1.f / (sqrtf(ss) + EPS_);
            v0.x *= inv; v0.y *= inv; v0.z *= inv; v0.w *= inv;
            v1.x *= inv; v1.y *= inv; v1.z *= inv; v1.w *= inv;
            dst[lane]      = v0;
            dst[lane + 32] = v1;
            __half2* d2 = reinterpret_cast<__half2*>(g_vec16 + base);
            d2[2 * lane + 0]  = __float22half2_rn(make_float2(v0.x, v0.y));
            d2[2 * lane + 1]  = __float22half2_rn(make_float2(v0.z, v0.w));
            d2[2 * lane + 64] = __float22half2_rn(make_float2(v1.x, v1.y));
            d2[2 * lane + 65] = __float22half2_rn(make_float2(v1.z, v1.w));
        }
    } else if (blk < 16368) {
        int idx = (blk - 8192) * 8 + w;   // need 128*511 = 65408
        if (idx < 128 * 511) {
            int b   = idx / 511;
            int row = 512 + idx % 511;
            size_t base = ((size_t)b * N_ + row) * D_;
            float4 z = make_float4(0.f, 0.f, 0.f, 0.f);
            float4* dst = reinterpret_cast<float4*>(g_vec + base);
            dst[lane] = z; dst[lane + 32] = z;
            reinterpret_cast<uint4*>(g_vec16 + base)[lane] = make_uint4(0u, 0u, 0u, 0u);
        }
    } else {
        if (blk == 16368 && threadIdx.x < B_) g_done[threadIdx.x] = 0;
        int idx = (blk - 16368) * 256 + threadIdx.x;   // 0..131071
        int row = idx >> 8;
        int k   = idx & 255;
        g_W16[idx] = __float2half((row < C_) ? W[row * 256 + k] : 0.f);
    }
}

// ---------------------------------------------------------------------------
// fp16 mma.sync m16n8k16 GEMM tile body (R11/R13 — best measured).
// ---------------------------------------------------------------------------
#define GS_H 40                      // smem row stride in halfs (32 + 8 pad)
#define STAGE_H (256 * GS_H)         // halfs per stage
#define GM_SMEM_BYTES (2 * STAGE_H * 2)   // 40960 B dynamic

__device__ __forceinline__ void cp16(uint32_t dst, const void* src) {
    asm volatile("cp.async.ca.shared.global [%0], [%1], 16;"
                 :: "r"(dst), "l"(src) : "memory");
}
__device__ __forceinline__ void cp_commit() {
    asm volatile("cp.async.commit_group;" ::: "memory");
}
__device__ __forceinline__ void cp_wait0() {
    asm volatile("cp.async.wait_group 0;" ::: "memory");
}
__device__ __forceinline__ void mma_f16(float* d, const uint32_t* a,
                                        uint32_t b0, uint32_t b1) {
    asm volatile(
        "mma.sync.aligned.m16n8k16.row.col.f32.f16.f16.f32 "
        "{%0,%1,%2,%3}, {%4,%5,%6,%7}, {%8,%9}, {%0,%1,%2,%3};"
        : "+f"(d[0]), "+f"(d[1]), "+f"(d[2]), "+f"(d[3])
        : "r"(a[0]), "r"(a[1]), "r"(a[2]), "r"(a[3]), "r"(b0), "r"(b1));
}

__device__ void gemm_tile(size_t m0, int n0,
                          const float* __restrict__ bias,
                          float* __restrict__ out) {
    extern __shared__ __half gm_smem[];
    const __half* A = g_vec16;
    int tid = threadIdx.x;
    int wid = tid >> 5;
    int lane = tid & 31;
    int qr = lane >> 2;
    int c4 = lane & 3;
    int wm = wid & 3;
    int wn = wid >> 2;

    int lrow = tid >> 1;
    int lseg = tid & 1;
    const __half* asrc = A + (m0 + lrow) * D_ + lseg * 16;
    const __half* bsrc = g_W16 + (size_t)(n0 + lrow) * D_ + lseg * 16;

    uint32_t smbase = smem_to_u32(gm_smem);
    uint32_t ldstA = smbase + (uint32_t)(lrow * GS_H + lseg * 16) * 2;
    uint32_t ldstB = ldstA + 128 * GS_H * 2;

#pragma unroll
    for (int q = 0; q < 2; ++q) {
        cp16(ldstA + q * 16, asrc + q * 8);
        cp16(ldstB + q * 16, bsrc + q * 8);
    }
    cp_commit();

    float acc[2][8][4];
#pragma unroll
    for (int mt = 0; mt < 2; ++mt)
#pragma unroll
        for (int nt = 0; nt < 8; ++nt)
#pragma unroll
            for (int u = 0; u < 4; ++u) acc[mt][nt][u] = 0.f;

    cp_wait0();
    __syncthreads();

    for (int bk = 0; bk < 8; ++bk) {
        int cur = bk & 1;
        if (bk < 7) {
            int nxt = cur ^ 1;
            uint32_t dA = ldstA + (uint32_t)(nxt * STAGE_H) * 2;
            uint32_t dB = ldstB + (uint32_t)(nxt * STAGE_H) * 2;
            const __half* as = asrc + (bk + 1) * 32;
            const __half* bs = bsrc + (bk + 1) * 32;
#pragma unroll
            for (int q = 0; q < 2; ++q) {
                cp16(dA + q * 16, as + q * 8);
                cp16(dB + q * 16, bs + q * 8);
            }
            cp_commit();
        }

        const __half* sA = gm_smem + cur * STAGE_H;
        const __half* sB = sA + 128 * GS_H;
        int ra = wm * 32 + qr;
        int nb = wn * 64 + qr;
#pragma unroll
        for (int sft = 0; sft < 2; ++sft) {
            int kb = 16 * sft + 2 * c4;
            uint32_t af[2][4];
#pragma unroll
            for (int mt = 0; mt < 2; ++mt) {
                int r0 = ra + mt * 16;
                af[mt][0] = *reinterpret_cast<const uint32_t*>(&sA[r0 * GS_H + kb]);
                af[mt][1] = *reinterpret_cast<const uint32_t*>(&sA[(r0 + 8) * GS_H + kb]);
                af[mt][2] = *reinterpret_cast<const uint32_t*>(&sA[r0 * GS_H + kb + 8]);
                af[mt][3] = *reinterpret_cast<const uint32_t*>(&sA[(r0 + 8) * GS_H + kb + 8]);
            }
#pragma unroll
            for (int nt = 0; nt < 8; ++nt) {
                int n = nb + nt * 8;
                uint32_t b0 = *reinterpret_cast<const uint32_t*>(&sB[n * GS_H + kb]);
                uint32_t b1 = *reinterpret_cast<const uint32_t*>(&sB[n * GS_H + kb + 8]);
                mma_f16(acc[0][nt], af[0], b0, b1);
                mma_f16(acc[1][nt], af[1], b0, b1);
            }
        }

        if (bk < 7) cp_wait0();
        __syncthreads();
    }

#pragma unroll
    for (int nt = 0; nt < 8; ++nt) {
        int col = n0 + wn * 64 + nt * 8 + 2 * c4;
        if (col >= C_) continue;
        bool c1ok = (col + 1) < C_;
        float b0v = bias[col];
        float b1v = c1ok ? bias[col + 1] : 0.f;
#pragma unroll
        for (int mt = 0; mt < 2; ++mt) {
            size_t m = m0 + wm * 32 + mt * 16 + qr;
            float* o0 = out + m * C_ + col;
            o0[0] = acc[mt][nt][0] + b0v;
            if (c1ok) o0[1] = acc[mt][nt][1] + b1v;
            float* o1 = out + (m + 8) * C_ + col;
            o1[0] = acc[mt][nt][2] + b0v;
            if (c1ok) o1[1] = acc[mt][nt][3] + b1v;
        }
    }
}

// ---------------------------------------------------------------------------
// Compose body (R16 — compacted steps, f32x2 inner loop, reduced barriers).
// ---------------------------------------------------------------------------
#define PK2(dst, lo, hi) \
    asm("mov.b64 %0, {%1, %2};" : "=l"(dst) : "f"(lo), "f"(hi))
#define UNPK2(lo, hi, src) \
    asm("mov.b64 {%0, %1}, %2;" : "=f"(lo), "=f"(hi) : "l"(src))
#define FMA2(acc, a, b) \
    asm("fma.rn.f32x2 %0, %1, %2, %0;" : "+l"(acc) : "l"(a), "l"(b))

__device__ void compose_body(int b, const int* __restrict__ comp) {
    __shared__ int sinfo[T_ * 4];        // compacted (type>0 only)
    __shared__ __align__(16) float sa[D_];
    __shared__ __align__(16) float sb[512];
    __shared__ float pt[4][320];
    __shared__ float red[8];
    __shared__ int warp_tot[8];
    __shared__ int s_base;

    int tid = threadIdx.x;
    float*  v   = g_vec   + (size_t)b * N_ * D_;
    __half* v16 = g_vec16 + (size_t)b * N_ * D_;
    const int* src = comp + (size_t)b * T_ * 4;

    // ---- compact out type-0 steps (ballot scan, order-preserving)
    if (tid == 0) s_base = 0;
    __syncthreads();
#pragma unroll 1
    for (int pass = 0; pass < 2; ++pass) {
        int e = pass * 256 + tid;
        int t0 = 0, t1 = 0, t2 = 0, t3 = 0;
        bool keep = false;
        if (e < T_) {
            t0 = src[4 * e]; t1 = src[4 * e + 1];
            t2 = src[4 * e + 2]; t3 = src[4 * e + 3];
            keep = (t0 > 0);
        }
        unsigned m = __ballot_sync(0xffffffffu, keep);
        int lane = tid & 31, w = tid >> 5;
        int lpre = __popc(m & ((1u << lane) - 1u));
        if (lane == 0) warp_tot[w] = __popc(m);
        __syncthreads();
        int woff = 0;
        for (int i = 0; i < w; ++i) woff += warp_tot[i];
        int base = s_base;
        if (keep) {
            int d = base + woff + lpre;
            sinfo[4 * d + 0] = t0; sinfo[4 * d + 1] = t1;
            sinfo[4 * d + 2] = t2; sinfo[4 * d + 3] = t3;
        }
        __syncthreads();
        if (tid == 0) {
            int tot = 0;
            for (int i = 0; i < 8; ++i) tot += warp_tot[i];
            s_base = base + tot;
        }
        __syncthreads();
    }
    const int Tc = s_base;
    __syncthreads();
    if (Tc == 0) return;

    const int t  = tid & 63;
    const int g  = tid >> 6;
    const int j0 = g * 64;
    const int ftid = tid + (tid >> 2);
    const uint32_t bA = smem_to_u32(sb) + (uint32_t)(j0 + 4 * t) * 4;
    const uint32_t aA = smem_to_u32(sa) + (uint32_t)j0 * 4;

    int typ = sinfo[0], p = sinfo[1], l = sinfo[2], r = sinfo[3];
    float av = v[(size_t)l * D_ + tid];
    float bv = v[(size_t)r * D_ + tid];

    for (int ts = 0; ts < Tc; ++ts) {
        int typ2 = 0, p2 = 0, l2 = 0, r2 = 0;
        float av2 = 0.f, bv2 = 0.f;
        if (ts + 1 < Tc) {
            typ2 = sinfo[4 * ts + 4];
            p2   = sinfo[4 * ts + 5];
            l2   = sinfo[4 * ts + 6];
            r2   = sinfo[4 * ts + 7];
            av2 = v[(size_t)l2 * D_ + tid];
            bv2 = v[(size_t)r2 * D_ + tid];
        }

        float outv;
        if (typ == 1) {
            outv = av;
            v[(size_t)p * D_ + tid] = outv;
            v16[(size_t)p * D_ + tid] = __float2half(outv);
        } else {   // typ == 2
            sa[tid] = av;
            sb[tid] = bv;
            sb[tid + 256] = bv;
            __syncthreads();

            unsigned long long acc0 = 0ull, acc1 = 0ull, acc2 = 0ull, acc3 = 0ull;
            unsigned long long P0, P1, Q0, Q1, O0, O1, O2, pe0, pe1;
            float p0l, p0h, p1l, p1h, q0l, q0h, q1l, q1h;
            asm("ld.shared.v2.u64 {%0,%1}, [%2];" : "=l"(P0), "=l"(P1) : "r"(bA));
            UNPK2(p0l, p0h, P0);
            UNPK2(p1l, p1h, P1);
            PK2(O0, p0h, p1l);
#pragma unroll
            for (int u = 0; u < 16; ++u) {
                asm("ld.shared.v2.u64 {%0,%1}, [%2];"
                    : "=l"(Q0), "=l"(Q1) : "r"(bA + 16u * (u + 1)));
                asm("ld.shared.v2.u64 {%0,%1}, [%2];"
                    : "=l"(pe0), "=l"(pe1) : "r"(aA + 16u * u));
                UNPK2(q0l, q0h, Q0);
                PK2(O1, p1h, q0l);
                FMA2(acc0, pe0, P0);
                FMA2(acc1, pe0, O0);
                FMA2(acc2, pe0, P1);
                FMA2(acc3, pe0, O1);
                UNPK2(q1l, q1h, Q1);
                PK2(O2, q0h, q1l);
                FMA2(acc0, pe1, P1);
                FMA2(acc1, pe1, O1);
                FMA2(acc2, pe1, Q0);
                FMA2(acc3, pe1, O2);
                P0 = Q0; P1 = Q1; O0 = O2; p1h = q1h;
            }
            float lo, hi, c0, c1, c2, c3;
            UNPK2(lo, hi, acc0); c0 = lo + hi;
            UNPK2(lo, hi, acc1); c1 = lo + hi;
            UNPK2(lo, hi, acc2); c2 = lo + hi;
            UNPK2(lo, hi, acc3); c3 = lo + hi;

            pt[g][5 * t + 0] = c0;
            pt[g][5 * t + 1] = c1;
            pt[g][5 * t + 2] = c2;
            pt[g][5 * t + 3] = c3;
            __syncthreads();

            float tot = pt[0][ftid] + pt[1][ftid] + pt[2][ftid] + pt[3][ftid];
            float ss = tot * tot;
#pragma unroll
            for (int o = 16; o > 0; o >>= 1)
                ss += __shfl_xor_sync(0xffffffffu, ss, o);
            if ((tid & 31) == 0) red[tid >> 5] = ss;
            __syncthreads();
            float tss = red[0] + red[1] + red[2] + red[3]
                      + red[4] + red[5] + red[6] + red[7];
            outv = tot / (sqrtf(tss) + EPS_);
            v[(size_t)p * D_ + tid] = outv;
            v16[(size_t)p * D_ + tid] = __float2half(outv);
        }

        if (ts + 1 < Tc) {
            if (l2 == p) av2 = outv;
            if (r2 == p) bv2 = outv;
        }
        typ = typ2; p = p2; l = l2; r = r2; av = av2; bv = bv2;
    }
}

// ---------------------------------------------------------------------------
// ONE fused compute kernel:
//  blocks [0, 128):       compose (batch = blockIdx), then publish g_done[b]
//  blocks [128, 2176):    leaf-half GEMM (rows [0,512), no dependency)
//  blocks [2176, 4224):   internal-half GEMM — spin-waits on g_done[b]
// Deadlock-free: compose blocks have the lowest indices -> all resident from
// the start (128 < 296 block slots), and they depend on nothing.
// ---------------------------------------------------------------------------
__global__ void __launch_bounds__(256, 2) fused_all(
    const int* __restrict__ comp,
    const float* __restrict__ bias,
    float* __restrict__ out) {
    if (blockIdx.x < B_) {
        int b = blockIdx.x;
        compose_body(b, comp);
        __threadfence();
        __syncthreads();
        if (threadIdx.x == 0) atomicExch(&g_done[b], 1);
    } else if (blockIdx.x < B_ + 2048) {
        int gidx = blockIdx.x - B_;        // 0..2047
        int n0 = (gidx & 3) * 128;
        int mt = gidx >> 2;                // 0..511
        int b  = mt >> 2;
        int ty = mt & 3;
        size_t m0 = (size_t)b * N_ + (size_t)ty * 128;   // leaf rows [0,512)
        gemm_tile(m0, n0, bias, out);
    } else {
        int gidx = blockIdx.x - B_ - 2048; // 0..2047
        int n0 = (gidx & 3) * 128;
        int mt = gidx >> 2;
        int b  = mt >> 2;
        int ty = mt & 3;
        size_t m0 = (size_t)b * N_ + (size_t)((ty < 3) ? 512 + ty * 128 : 895);
        if (threadIdx.x == 0) {
            while (atomicAdd(&g_done[b], 0) == 0) __nanosleep(200);
        }
        __syncthreads();
        __threadfence();
        gemm_tile(m0, n0, bias, out);
    }
}

// ---------------------------------------------------------------------------
extern "C" void kernel_launch(void* const* d_in, const int* in_sizes, int n_in,
                              void* d_out, int out_size) {
    const int*   leaf_id = (const int*)d_in[1];    // (B,L,2) int32
    const int*   mask    = (const int*)d_in[2];    // (B,L)   int32
    const int*   comp    = (const int*)d_in[3];    // (B,T,4) int32
    const float* emb     = (const float*)d_in[4];  // (V,D)
    const float* W       = (const float*)d_in[5];  // (C,D)
    const float* bias    = (const float*)d_in[6];  // (C,)
    float* out = (float*)d_out;                    // (B,N,C)

    static bool attr_set = false;
    if (!attr_set) {
        cudaFuncSetAttribute(fused_all,
                             cudaFuncAttributeMaxDynamicSharedMemorySize,
                             GM_SMEM_BYTES);
        attr_set = true;
    }

    // one dependency-free prologue (embed leaves + zero internal + pack W + flags)
    init_kernel<<<16880, 256>>>(leaf_id, mask, emb, W);

    // one fused compute launch: compose + leaf GEMM + flag-gated internal GEMM
    fused_all<<<B_ + 4096, 256, GM_SMEM_BYTES>>>(comp, bias, out);
}